// round 13
// baseline (speedup 1.0000x reference)
#include <cuda_runtime.h>
#include <cstdint>

#define N_      16384
#define K_      64
#define F_      2048
#define NCHUNK  2            // column chunks of 1024 floats
#define CHUNK   1024
#define TPB     128          // each thread owns 8 floats (32B) of the chunk
#define S_      8            // row segments per cluster
#define D_      8            // cp.async row stages (8 x 4KB = 32KB)
#define AB_     256          // assign blocks in setup_k
#define PB_     256          // prep blocks in setup_k
#define ALPHA_F 1.0f
#define GAMMA_F 1.0f

// ---- scratch (static device globals: allocation-free, zero-initialized) ----
__device__ int   g_rows[K_ * N_];        // per-cluster member row lists
__device__ int   g_cnt[K_];              // member counts (reset by main_k)
__device__ float g_rs[K_];               // pairwise dist row-sums (reset by main_k)
__device__ int   g_pdone[K_];            // prep arrival (self-reset)
__device__ float g_ak[K_];               // cw[k] / (rs[k]+alpha)
__device__ float g_invden[K_];           // 1 / (rs[k]+alpha)
__device__ float g_sx[K_ * F_];          // atomic column-sum accumulators
__device__ int   g_done[K_ * NCHUNK];    // per-(k,chunk) epilogue arrival (self-reset)
__device__ int   g_kdone[K_];            // per-k global arrival (self-reset)

__device__ __forceinline__ void cp16(unsigned s, const float* g) {
    asm volatile("cp.async.cg.shared.global [%0], [%1], 16;"
                 :: "r"(s), "l"(g) : "memory");
}
__device__ __forceinline__ void cp_commit() {
    asm volatile("cp.async.commit_group;" ::: "memory");
}

// ---------------------------------------------------------------------------
// setup_k: ONE kernel, two independent block families (unchanged, known-good).
// ---------------------------------------------------------------------------
__global__ void __launch_bounds__(256) setup_k(const float* __restrict__ C,
                                               const float* __restrict__ cw,
                                               const float* __restrict__ labels,
                                               float* __restrict__ loss) {
    int b = blockIdx.x, tid = threadIdx.x;
    if (b < AB_) {
        int t = b * 256 + tid;                       // 65536 threads
        reinterpret_cast<float2*>(g_sx)[t] = make_float2(0.f, 0.f);

        int row = t >> 2, part = t & 3;
        const float4* p =
            reinterpret_cast<const float4*>(labels + row * K_) + part * 4;
        float acc = 0.f;
#pragma unroll
        for (int j = 0; j < 4; j++) {
            float4 v = p[j];
            float base = (float)(part * 16 + j * 4);
            acc += v.x * base + v.y * (base + 1.f)
                 + v.z * (base + 2.f) + v.w * (base + 3.f);
        }
        acc += __shfl_xor_sync(0xFFFFFFFFu, acc, 1);
        acc += __shfl_xor_sync(0xFFFFFFFFu, acc, 2);
        if (part == 0) {
            int k = (int)(acc + 0.5f);
            int slot = atomicAdd(&g_cnt[k], 1);
            g_rows[k * N_ + slot] = row;
            loss[row] = 0.f;
        }
    } else {
        int pb = b - AB_;
        int k = pb >> 2, c = pb & 3;
        int col = c * 512 + 2 * tid;
        float2 a = *reinterpret_cast<const float2*>(C + k * F_ + col);
        float acc = 0.f;
#pragma unroll 8
        for (int j = 0; j < K_; j++) {
            float2 bv = *reinterpret_cast<const float2*>(C + j * F_ + col);
            float d0 = a.x - bv.x, d1 = a.y - bv.y;
            acc += d0 * d0 + d1 * d1;
        }
#pragma unroll
        for (int o = 16; o; o >>= 1)
            acc += __shfl_xor_sync(0xFFFFFFFFu, acc, o);
        __shared__ float sw_[8];
        int w = tid >> 5, l = tid & 31;
        if (l == 0) sw_[w] = acc;
        __syncthreads();
        if (tid == 0) {
            float bs = 0.f;
#pragma unroll
            for (int i = 0; i < 8; i++) bs += sw_[i];
            atomicAdd(&g_rs[k], bs);
            __threadfence();
            if (atomicAdd(&g_pdone[k], 1) == 3) {
                float rs = *(volatile float*)&g_rs[k];
                float inv = 1.f / (rs + ALPHA_F);
                g_invden[k] = inv;
                g_ak[k]     = cw[k] * inv;
                g_pdone[k]  = 0;
            }
        }
    }
}

// ---------------------------------------------------------------------------
// main_k: block (chunk c, cluster k, segment s). 8-stage cp.async ring with a
// CONSTANT-OUTSTANDING commit scheme (empty commits pad the tail), consumed
// 4 rows at a time with the 9-shuffle multi-row reduce (2.25 shfl/row vs 5)
// to shorten the per-warp serial chain ~3x. Row ids via uniform __ldg
// broadcast (no srows smem tile, no per-tile barriers).
// ---------------------------------------------------------------------------
__global__ void __launch_bounds__(TPB, 7) main_k(const float* __restrict__ X,
                                                 const float* __restrict__ C,
                                                 float* __restrict__ out) {
    __shared__ float buf[D_ * CHUNK];   // 32 KB
    __shared__ int   amLast;

    int c   = blockIdx.x;
    int k   = blockIdx.y;
    int seg = blockIdx.z;
    int tid = threadIdx.x;
    int l   = tid & 31;
    int colt = c * CHUNK + tid * 8;

    float4 ck0 = *reinterpret_cast<const float4*>(C + k * F_ + colt);
    float4 ck1 = *reinterpret_cast<const float4*>(C + k * F_ + colt + 4);
    float4 ac0 = make_float4(0.f, 0.f, 0.f, 0.f);
    float4 ac1 = make_float4(0.f, 0.f, 0.f, 0.f);

    int   cnt  = g_cnt[k];
    float invd = g_invden[k];
    float* loss = out;                          // loss at out[0..N)

    int r0 = (cnt * seg) / S_;
    int r1 = (cnt * (seg + 1)) / S_;
    int total = r1 - r0;
    const int* rl = g_rows + k * N_ + r0;

    unsigned sb = (unsigned)__cvta_generic_to_shared(buf) + tid * 32u;

    if (total > 0) {
        // prologue: commit exactly D_ groups (empty past the end)
#pragma unroll
        for (int s = 0; s < D_; s++) {
            if (s < total) {
                const float* g = X + (size_t)__ldg(rl + s) * F_ + colt;
                unsigned a = sb + (unsigned)s * (CHUNK * 4u);
                cp16(a, g); cp16(a + 16u, g + 4);
            }
            cp_commit();
        }

        for (int r = 0; r < total; r += 4) {
            // outstanding is always D_=8 here; wait until oldest 4 are done
            asm volatile("cp.async.wait_group 4;" ::: "memory");
            int st = r & 7;                      // r%4==0 -> st in {0,4}
            int nproc = total - r; if (nproc > 4) nproc = 4;

            if (nproc == 4) {
                float s4[4];
                int rows4[4];
#pragma unroll
                for (int j = 0; j < 4; j++) {
                    rows4[j] = __ldg(rl + r + j);
                    const float4* bp = reinterpret_cast<const float4*>(
                        buf + (st + j) * CHUNK + tid * 8);
                    float4 x0 = bp[0], x1 = bp[1];
                    float d0 = x0.x - ck0.x, d1 = x0.y - ck0.y;
                    float d2 = x0.z - ck0.z, d3 = x0.w - ck0.w;
                    float d4 = x1.x - ck1.x, d5 = x1.y - ck1.y;
                    float d6 = x1.z - ck1.z, d7 = x1.w - ck1.w;
                    s4[j] = d0 * d0 + d1 * d1 + d2 * d2 + d3 * d3
                          + d4 * d4 + d5 * d5 + d6 * d6 + d7 * d7;
                    ac0.x += x0.x; ac0.y += x0.y; ac0.z += x0.z; ac0.w += x0.w;
                    ac1.x += x1.x; ac1.y += x1.y; ac1.z += x1.z; ac1.w += x1.w;
                }
                // 4-value reduce across 32 lanes: 9 shuffles (validated R8)
                float cc[2];
#pragma unroll
                for (int p = 0; p < 2; p++) {
                    float t0 = __shfl_xor_sync(0xFFFFFFFFu, s4[2 * p], 16);
                    float t1 = __shfl_xor_sync(0xFFFFFFFFu, s4[2 * p + 1], 16);
                    cc[p] = (l & 16) ? (s4[2 * p + 1] + t1) : (s4[2 * p] + t0);
                }
                float t0 = __shfl_xor_sync(0xFFFFFFFFu, cc[0], 8);
                float t1 = __shfl_xor_sync(0xFFFFFFFFu, cc[1], 8);
                float e  = (l & 8) ? (cc[1] + t1) : (cc[0] + t0);
                e += __shfl_xor_sync(0xFFFFFFFFu, e, 4);
                e += __shfl_xor_sync(0xFFFFFFFFu, e, 2);
                e += __shfl_xor_sync(0xFFFFFFFFu, e, 1);
                if ((l & 7) == 0) {
                    int j = ((l >> 4) & 1) | (((l >> 3) & 1) << 1); // 0,2,1,3
                    int rid = (j == 0) ? rows4[0] : (j == 1) ? rows4[1]
                             : (j == 2) ? rows4[2] : rows4[3];
                    atomicAdd(loss + rid, e * invd);
                }
            } else {
                for (int j = 0; j < nproc; j++) {
                    int rid = __ldg(rl + r + j);
                    const float4* bp = reinterpret_cast<const float4*>(
                        buf + (st + j) * CHUNK + tid * 8);
                    float4 x0 = bp[0], x1 = bp[1];
                    float d0 = x0.x - ck0.x, d1 = x0.y - ck0.y;
                    float d2 = x0.z - ck0.z, d3 = x0.w - ck0.w;
                    float d4 = x1.x - ck1.x, d5 = x1.y - ck1.y;
                    float d6 = x1.z - ck1.z, d7 = x1.w - ck1.w;
                    float s = d0 * d0 + d1 * d1 + d2 * d2 + d3 * d3
                            + d4 * d4 + d5 * d5 + d6 * d6 + d7 * d7;
                    ac0.x += x0.x; ac0.y += x0.y; ac0.z += x0.z; ac0.w += x0.w;
                    ac1.x += x1.x; ac1.y += x1.y; ac1.z += x1.z; ac1.w += x1.w;
#pragma unroll
                    for (int o = 16; o; o >>= 1)
                        s += __shfl_xor_sync(0xFFFFFFFFu, s, o);
                    if (l == 0) atomicAdd(loss + rid, s * invd);
                }
            }

            // refill consumed stages with rows r+8..r+11 (empty commits pad)
#pragma unroll
            for (int j = 0; j < 4; j++) {
                int nr = r + D_ + j;
                if (nr < total) {
                    const float* g = X + (size_t)__ldg(rl + nr) * F_ + colt;
                    unsigned a = sb + (unsigned)(st + j) * (CHUNK * 4u);
                    cp16(a, g); cp16(a + 16u, g + 4);
                }
                cp_commit();
            }
        }
        asm volatile("cp.async.wait_group 0;" ::: "memory");
    }

    // accumulate segment partials into g_sx
    float* sx = g_sx + k * F_ + colt;
    atomicAdd(sx + 0, ac0.x); atomicAdd(sx + 1, ac0.y);
    atomicAdd(sx + 2, ac0.z); atomicAdd(sx + 3, ac0.w);
    atomicAdd(sx + 4, ac1.x); atomicAdd(sx + 5, ac1.y);
    atomicAdd(sx + 6, ac1.z); atomicAdd(sx + 7, ac1.w);

    // fence + block barrier BEFORE arrival (R12 race fix — keep)
    __threadfence();
    __syncthreads();
    if (tid == 0)
        amLast = (atomicAdd(&g_done[k * NCHUNK + c], 1) == S_ - 1);
    __syncthreads();
    if (amLast) {
        float4 s0 = __ldcg(reinterpret_cast<const float4*>(sx));
        float4 s1 = __ldcg(reinterpret_cast<const float4*>(sx) + 1);
        float ga = GAMMA_F * g_ak[k];
        float fc = (float)cnt;
        float4 o0, o1;
        o0.x = ck0.x - ga * (s0.x - fc * ck0.x);
        o0.y = ck0.y - ga * (s0.y - fc * ck0.y);
        o0.z = ck0.z - ga * (s0.z - fc * ck0.z);
        o0.w = ck0.w - ga * (s0.w - fc * ck0.w);
        o1.x = ck1.x - ga * (s1.x - fc * ck1.x);
        o1.y = ck1.y - ga * (s1.y - fc * ck1.y);
        o1.z = ck1.z - ga * (s1.z - fc * ck1.z);
        o1.w = ck1.w - ga * (s1.w - fc * ck1.w);
        *reinterpret_cast<float4*>(out + N_ + k * F_ + colt)     = o0;
        *reinterpret_cast<float4*>(out + N_ + k * F_ + colt + 4) = o1;
        if (tid == 0) g_done[k * NCHUNK + c] = 0;   // reset for graph replay
    }

    // globally-last block of cluster k resets per-k state for next replay.
    if (tid == 0) {
        if (atomicAdd(&g_kdone[k], 1) == S_ * NCHUNK - 1) {
            g_kdone[k] = 0;
            g_cnt[k]   = 0;
            g_rs[k]    = 0.f;
        }
    }
}

extern "C" void kernel_launch(void* const* d_in, const int* in_sizes, int n_in,
                              void* d_out, int out_size) {
    const float* X  = (const float*)d_in[0];   // features [N,F]
    const float* L  = (const float*)d_in[1];   // labels   [N,K] one-hot
    const float* C  = (const float*)d_in[2];   // cluster  [K,F]
    const float* CW = (const float*)d_in[3];   // class_weight [K]
    float* out = (float*)d_out;                // [loss(N) | new_cluster(K*F)]

    setup_k <<<AB_ + PB_, 256>>>(C, CW, L, out);
    main_k  <<<dim3(NCHUNK, K_, S_), TPB>>>(X, C, out);
}